// round 6
// baseline (speedup 1.0000x reference)
#include <cuda_runtime.h>
#include <math.h>

#define BB 4
#define TT 2048
#define DD 1024
#define HH 16
#define HDIM 64
#define MM (BB*TT)   // 8192

// Scratch (device globals — no allocations allowed)
__device__ float g_q[BB*HH*TT*HDIM];   // [B,H,T,HD] 32MB
__device__ float g_k[BB*HH*TT*HDIM];
__device__ float g_v[BB*HH*TT*HDIM];
__device__ float g_o[BB*TT*HH*HDIM];   // [B,T,H*HD] 32MB

// Single-instruction exp2 (MUFU.EX2) independent of nvcc fast-math flags.
__device__ __forceinline__ float ex2(float x) {
    float r;
    asm("ex2.approx.ftz.f32 %0, %1;" : "=f"(r) : "f"(x));
    return r;
}

// ---------------------------------------------------------------------------
// Kernel 1: QKV projection.  For each (mat in {q,k,v}, head h):
//   out[8192, 64] = X[8192, 1024] @ W_h[1024, 64]
// BM=256, BN=64, BK=16, 256 threads, 8x8 accumulators, double-buffered SMEM.
// ---------------------------------------------------------------------------
__global__ __launch_bounds__(256) void qkv_kernel(
    const float* __restrict__ x,
    const float* __restrict__ Wq,
    const float* __restrict__ Wk,
    const float* __restrict__ Wv)
{
    __shared__ float As[2][256][17];   // 34816 B
    __shared__ float Ws[2][16][65];    //  8320 B

    const int tid = threadIdx.x;
    const int mat = blockIdx.y >> 4;    // 0=q,1=k,2=v
    const int h   = blockIdx.y & 15;
    const float* W = (mat == 0 ? Wq : (mat == 1 ? Wk : Wv)) + (size_t)h * DD * HDIM;
    float* outp = (mat == 0 ? g_q : (mat == 1 ? g_k : g_v));

    const int m0 = blockIdx.x * 256;
    const int tx = tid & 7;       // 8 col groups
    const int ty = tid >> 3;      // 32 row groups
    const int r0 = ty * 8;
    const int c0 = tx * 8;

    const int a_row = tid >> 2;        // base row (per 64-row chunk)
    const int a_c4  = tid & 3;
    const int w_row = tid >> 4;
    const int w_c4  = tid & 15;

    float acc[8][8];
#pragma unroll
    for (int i = 0; i < 8; i++)
#pragma unroll
        for (int j = 0; j < 8; j++) acc[i][j] = 0.0f;

    // Preload k0 = 0 into buffer 0
    {
#pragma unroll
        for (int l = 0; l < 4; l++) {
            int row = l * 64 + a_row;
            float4 v = *(const float4*)&x[(size_t)(m0 + row) * DD + a_c4 * 4];
            As[0][row][a_c4 * 4 + 0] = v.x;
            As[0][row][a_c4 * 4 + 1] = v.y;
            As[0][row][a_c4 * 4 + 2] = v.z;
            As[0][row][a_c4 * 4 + 3] = v.w;
        }
        float4 v = *(const float4*)&W[(size_t)w_row * HDIM + w_c4 * 4];
        Ws[0][w_row][w_c4 * 4 + 0] = v.x;
        Ws[0][w_row][w_c4 * 4 + 1] = v.y;
        Ws[0][w_row][w_c4 * 4 + 2] = v.z;
        Ws[0][w_row][w_c4 * 4 + 3] = v.w;
    }
    __syncthreads();

    int buf = 0;
    for (int k0 = 0; k0 < DD; k0 += 16) {
        const bool has_next = (k0 + 16) < DD;
        float4 rA[4], rW;
        if (has_next) {
#pragma unroll
            for (int l = 0; l < 4; l++) {
                int row = l * 64 + a_row;
                rA[l] = *(const float4*)&x[(size_t)(m0 + row) * DD + (k0 + 16) + a_c4 * 4];
            }
            rW = *(const float4*)&W[(size_t)(k0 + 16 + w_row) * HDIM + w_c4 * 4];
        }

#pragma unroll
        for (int kk = 0; kk < 16; kk++) {
            float a[8], b[8];
#pragma unroll
            for (int i = 0; i < 8; i++) a[i] = As[buf][r0 + i][kk];
#pragma unroll
            for (int j = 0; j < 8; j++) b[j] = Ws[buf][kk][c0 + j];
#pragma unroll
            for (int i = 0; i < 8; i++)
#pragma unroll
                for (int j = 0; j < 8; j++) acc[i][j] = fmaf(a[i], b[j], acc[i][j]);
        }

        if (has_next) {
            int nb = buf ^ 1;
#pragma unroll
            for (int l = 0; l < 4; l++) {
                int row = l * 64 + a_row;
                As[nb][row][a_c4 * 4 + 0] = rA[l].x;
                As[nb][row][a_c4 * 4 + 1] = rA[l].y;
                As[nb][row][a_c4 * 4 + 2] = rA[l].z;
                As[nb][row][a_c4 * 4 + 3] = rA[l].w;
            }
            Ws[nb][w_row][w_c4 * 4 + 0] = rW.x;
            Ws[nb][w_row][w_c4 * 4 + 1] = rW.y;
            Ws[nb][w_row][w_c4 * 4 + 2] = rW.z;
            Ws[nb][w_row][w_c4 * 4 + 3] = rW.w;
            __syncthreads();
            buf = nb;
        }
    }

    // Store to [B,H,T,HD]
    const int b_ = m0 / TT;
    const int t0 = m0 % TT;
    const int bh = b_ * HH + h;
    float* obase = outp + ((size_t)bh * TT + t0) * HDIM;
#pragma unroll
    for (int i = 0; i < 8; i++) {
        float4 v0 = make_float4(acc[i][0], acc[i][1], acc[i][2], acc[i][3]);
        float4 v1 = make_float4(acc[i][4], acc[i][5], acc[i][6], acc[i][7]);
        *(float4*)&obase[(size_t)(r0 + i) * HDIM + c0]     = v0;
        *(float4*)&obase[(size_t)(r0 + i) * HDIM + c0 + 4] = v1;
    }
}

// ---------------------------------------------------------------------------
// Kernel 2: causal flash attention, fp32 online softmax in base-2 domain.
// Grid: (32 q-tiles, 64 bh).  Block: 256 threads.
// Thread (r = tid>>2, g = tid&3) owns query row r, dims/cols [g*16, g*16+16).
// Q (pre-scaled by log2(e)/sqrt(HD)) in registers, shfl-broadcast across the
// 4-lane group; K transposed in SMEM; P broadcast by shfl (never in SMEM).
// SMEM loads in both hot loops are g-only addressed -> warp-broadcast (N=1).
// K/V tiles for step kt+1 are register-prefetched during compute on step kt.
// ---------------------------------------------------------------------------
__global__ __launch_bounds__(256) void attn_kernel()
{
    __shared__ float Kts[HDIM][68];  // [dim][key], padded
    __shared__ float Vs[64][64];     // [key][dim]

    const int tid = threadIdx.x;
    const int r = tid >> 2;
    const int g = tid & 3;
    const int qt = gridDim.x - 1 - blockIdx.x;  // heavy diagonals first
    const int bh = blockIdx.y;

    const float* kbp = g_k + (size_t)bh * TT * HDIM;
    const float* vbp = g_v + (size_t)bh * TT * HDIM;
    const int qrow = qt * 64 + r;
    // scale = log2(e) / sqrt(64): softmax computed as 2^(s - m) with s in
    // log2-units, identical to exp((qk/8) - m_e) since 2^(x*log2e) == e^x.
    const float scale = 0.125f * 1.4426950408889634f;

    // Per-thread tile-load coordinates: 4 (s, e4) chunks
    const int ld_s  = tid >> 4;   // 0..15 (base key row per 16-row chunk)
    const int ld_e4 = tid & 15;   // 0..15 (float4 slot within 64-dim row)

    // Q row slice into registers, pre-scaled
    float qreg[16];
    {
        const float* qp = g_q + ((size_t)bh * TT + qrow) * HDIM + g * 16;
#pragma unroll
        for (int i = 0; i < 4; i++) {
            float4 v = *(const float4*)(qp + i * 4);
            qreg[i * 4 + 0] = v.x * scale; qreg[i * 4 + 1] = v.y * scale;
            qreg[i * 4 + 2] = v.z * scale; qreg[i * 4 + 3] = v.w * scale;
        }
    }

    float o[16];
#pragma unroll
    for (int i = 0; i < 16; i++) o[i] = 0.0f;
    float m_prev = -1e30f;
    float l = 0.0f;

    // Prefetch tile 0 into registers
    float4 pK[4], pV[4];
#pragma unroll
    for (int l4 = 0; l4 < 4; l4++) {
        int s = l4 * 16 + ld_s;
        pK[l4] = *(const float4*)&kbp[(size_t)s * HDIM + ld_e4 * 4];
        pV[l4] = *(const float4*)&vbp[(size_t)s * HDIM + ld_e4 * 4];
    }

    for (int kt = 0; kt <= qt; kt++) {
        // Store prefetched regs into SMEM (K transposed)
#pragma unroll
        for (int l4 = 0; l4 < 4; l4++) {
            int s = l4 * 16 + ld_s;
            Kts[ld_e4 * 4 + 0][s] = pK[l4].x;
            Kts[ld_e4 * 4 + 1][s] = pK[l4].y;
            Kts[ld_e4 * 4 + 2][s] = pK[l4].z;
            Kts[ld_e4 * 4 + 3][s] = pK[l4].w;
            *(float4*)&Vs[s][ld_e4 * 4] = pV[l4];
        }
        __syncthreads();

        // Issue prefetch for next tile (results consumed after compute+sync)
        if (kt < qt) {
#pragma unroll
            for (int l4 = 0; l4 < 4; l4++) {
                int s = (kt + 1) * 64 + l4 * 16 + ld_s;
                pK[l4] = *(const float4*)&kbp[(size_t)s * HDIM + ld_e4 * 4];
                pV[l4] = *(const float4*)&vbp[(size_t)s * HDIM + ld_e4 * 4];
            }
        }

        // Scores: sacc[j] = sum_k Q[r][k] * K[kt*64 + g*16+j][k]  (log2-units)
        float sacc[16];
#pragma unroll
        for (int j = 0; j < 16; j++) sacc[j] = 0.0f;
#pragma unroll
        for (int kb4 = 0; kb4 < 4; kb4++) {
#pragma unroll
            for (int ki = 0; ki < 16; ki++) {
                float qv = __shfl_sync(0xffffffffu, qreg[ki], kb4, 4);
                int k = kb4 * 16 + ki;
                float4 k0 = *(const float4*)&Kts[k][g * 16 + 0];
                float4 k1 = *(const float4*)&Kts[k][g * 16 + 4];
                float4 k2 = *(const float4*)&Kts[k][g * 16 + 8];
                float4 k3 = *(const float4*)&Kts[k][g * 16 + 12];
                sacc[0]  = fmaf(qv, k0.x, sacc[0]);
                sacc[1]  = fmaf(qv, k0.y, sacc[1]);
                sacc[2]  = fmaf(qv, k0.z, sacc[2]);
                sacc[3]  = fmaf(qv, k0.w, sacc[3]);
                sacc[4]  = fmaf(qv, k1.x, sacc[4]);
                sacc[5]  = fmaf(qv, k1.y, sacc[5]);
                sacc[6]  = fmaf(qv, k1.z, sacc[6]);
                sacc[7]  = fmaf(qv, k1.w, sacc[7]);
                sacc[8]  = fmaf(qv, k2.x, sacc[8]);
                sacc[9]  = fmaf(qv, k2.y, sacc[9]);
                sacc[10] = fmaf(qv, k2.z, sacc[10]);
                sacc[11] = fmaf(qv, k2.w, sacc[11]);
                sacc[12] = fmaf(qv, k3.x, sacc[12]);
                sacc[13] = fmaf(qv, k3.y, sacc[13]);
                sacc[14] = fmaf(qv, k3.z, sacc[14]);
                sacc[15] = fmaf(qv, k3.w, sacc[15]);
            }
        }

        // Causal mask (diagonal tile only; scale already folded into Q)
        if (kt == qt) {
#pragma unroll
            for (int j = 0; j < 16; j++) {
                int s_local = g * 16 + j;
                if (s_local > r) sacc[j] = -1e30f;
            }
        }

        // Online softmax in base-2 (row state shared across the 4-lane group)
        float mloc = sacc[0];
#pragma unroll
        for (int j = 1; j < 16; j++) mloc = fmaxf(mloc, sacc[j]);
        mloc = fmaxf(mloc, __shfl_xor_sync(0xffffffffu, mloc, 1));
        mloc = fmaxf(mloc, __shfl_xor_sync(0xffffffffu, mloc, 2));
        float m_new = fmaxf(m_prev, mloc);
        float corr = ex2(m_prev - m_new);
        float sum = 0.0f;
#pragma unroll
        for (int j = 0; j < 16; j++) {
            sacc[j] = ex2(sacc[j] - m_new);
            sum += sacc[j];
        }
        sum += __shfl_xor_sync(0xffffffffu, sum, 1);
        sum += __shfl_xor_sync(0xffffffffu, sum, 2);
        l = l * corr + sum;
#pragma unroll
        for (int j = 0; j < 16; j++) o[j] *= corr;
        m_prev = m_new;

        // O += P @ V  (P broadcast within the 4-lane row group via shfl)
#pragma unroll
        for (int sb = 0; sb < 4; sb++) {
#pragma unroll
            for (int si = 0; si < 16; si++) {
                float p = __shfl_sync(0xffffffffu, sacc[si], sb, 4);
                int s = sb * 16 + si;
                float4 v0 = *(const float4*)&Vs[s][g * 16 + 0];
                float4 v1 = *(const float4*)&Vs[s][g * 16 + 4];
                float4 v2 = *(const float4*)&Vs[s][g * 16 + 8];
                float4 v3 = *(const float4*)&Vs[s][g * 16 + 12];
                o[0]  = fmaf(p, v0.x, o[0]);
                o[1]  = fmaf(p, v0.y, o[1]);
                o[2]  = fmaf(p, v0.z, o[2]);
                o[3]  = fmaf(p, v0.w, o[3]);
                o[4]  = fmaf(p, v1.x, o[4]);
                o[5]  = fmaf(p, v1.y, o[5]);
                o[6]  = fmaf(p, v1.z, o[6]);
                o[7]  = fmaf(p, v1.w, o[7]);
                o[8]  = fmaf(p, v2.x, o[8]);
                o[9]  = fmaf(p, v2.y, o[9]);
                o[10] = fmaf(p, v2.z, o[10]);
                o[11] = fmaf(p, v2.w, o[11]);
                o[12] = fmaf(p, v3.x, o[12]);
                o[13] = fmaf(p, v3.y, o[13]);
                o[14] = fmaf(p, v3.z, o[14]);
                o[15] = fmaf(p, v3.w, o[15]);
            }
        }
        __syncthreads();  // all reads of this tile done before overwrite
    }

    // Normalize and write to [B,T,H*HD] concat layout
    const float inv = 1.0f / l;
    const int b_ = bh >> 4;
    const int h  = bh & 15;
    float* op = g_o + (((size_t)(b_ * TT + qrow)) * HH + h) * HDIM + g * 16;
#pragma unroll
    for (int i = 0; i < 4; i++) {
        float4 v = make_float4(o[i * 4 + 0] * inv, o[i * 4 + 1] * inv,
                               o[i * 4 + 2] * inv, o[i * 4 + 3] * inv);
        *(float4*)(op + i * 4) = v;
    }
}

// ---------------------------------------------------------------------------
// Kernel 3: output projection.  out[8192,1024] = g_o[8192,1024] @ Wp[1024,1024] + bp
// BM=128, BN=128, BK=16, 256 threads, 8x8 accumulators, double-buffered SMEM.
// ---------------------------------------------------------------------------
__global__ __launch_bounds__(256) void proj_kernel(
    const float* __restrict__ Wp,
    const float* __restrict__ bp,
    float* __restrict__ out)
{
    __shared__ float As[2][128][17];   // 17408 B
    __shared__ float Ws[2][16][129];   // 16512 B

    const int tid = threadIdx.x;
    const int m0 = blockIdx.x * 128;
    const int n0 = blockIdx.y * 128;
    const int tx = tid & 15;      // 16 col groups
    const int ty = tid >> 4;      // 16 row groups
    const int r0 = ty * 8;
    const int c0 = tx * 8;

    const int a_row = tid >> 2;   // 0..63
    const int a_c4  = tid & 3;
    const int w_row = tid >> 5;   // 0..7
    const int w_c4  = tid & 31;

    float acc[8][8];
#pragma unroll
    for (int i = 0; i < 8; i++)
#pragma unroll
        for (int j = 0; j < 8; j++) acc[i][j] = 0.0f;

    // Preload k0 = 0
    {
#pragma unroll
        for (int l = 0; l < 2; l++) {
            int row = l * 64 + a_row;
            float4 v = *(const float4*)&g_o[(size_t)(m0 + row) * DD + a_c4 * 4];
            As[0][row][a_c4 * 4 + 0] = v.x;
            As[0][row][a_c4 * 4 + 1] = v.y;
            As[0][row][a_c4 * 4 + 2] = v.z;
            As[0][row][a_c4 * 4 + 3] = v.w;
        }
#pragma unroll
        for (int l = 0; l < 2; l++) {
            int krow = l * 8 + w_row;
            float4 v = *(const float4*)&Wp[(size_t)krow * DD + n0 + w_c4 * 4];
            Ws[0][krow][w_c4 * 4 + 0] = v.x;
            Ws[0][krow][w_c4 * 4 + 1] = v.y;
            Ws[0][krow][w_c4 * 4 + 2] = v.z;
            Ws[0][krow][w_c4 * 4 + 3] = v.w;
        }
    }
    __syncthreads();

    int buf = 0;
    for (int k0 = 0; k0 < DD; k0 += 16) {
        const bool has_next = (k0 + 16) < DD;
        float4 rA[2], rW[2];
        if (has_next) {
#pragma unroll
            for (int l = 0; l < 2; l++) {
                int row = l * 64 + a_row;
                rA[l] = *(const float4*)&g_o[(size_t)(m0 + row) * DD + (k0 + 16) + a_c4 * 4];
            }
#pragma unroll
            for (int l = 0; l < 2; l++) {
                int krow = l * 8 + w_row;
                rW[l] = *(const float4*)&Wp[(size_t)(k0 + 16 + krow) * DD + n0 + w_c4 * 4];
            }
        }

#pragma unroll
        for (int kk = 0; kk < 16; kk++) {
            float a[8], b[8];
#pragma unroll
            for (int i = 0; i < 8; i++) a[i] = As[buf][r0 + i][kk];
#pragma unroll
            for (int j = 0; j < 8; j++) b[j] = Ws[buf][kk][c0 + j];
#pragma unroll
            for (int i = 0; i < 8; i++)
#pragma unroll
                for (int j = 0; j < 8; j++) acc[i][j] = fmaf(a[i], b[j], acc[i][j]);
        }

        if (has_next) {
            int nb = buf ^ 1;
#pragma unroll
            for (int l = 0; l < 2; l++) {
                int row = l * 64 + a_row;
                As[nb][row][a_c4 * 4 + 0] = rA[l].x;
                As[nb][row][a_c4 * 4 + 1] = rA[l].y;
                As[nb][row][a_c4 * 4 + 2] = rA[l].z;
                As[nb][row][a_c4 * 4 + 3] = rA[l].w;
            }
#pragma unroll
            for (int l = 0; l < 2; l++) {
                int krow = l * 8 + w_row;
                Ws[nb][krow][w_c4 * 4 + 0] = rW[l].x;
                Ws[nb][krow][w_c4 * 4 + 1] = rW[l].y;
                Ws[nb][krow][w_c4 * 4 + 2] = rW[l].z;
                Ws[nb][krow][w_c4 * 4 + 3] = rW[l].w;
            }
            __syncthreads();
            buf = nb;
        }
    }

    float bias[8];
#pragma unroll
    for (int j = 0; j < 8; j++) bias[j] = bp[n0 + c0 + j];
#pragma unroll
    for (int i = 0; i < 8; i++) {
        float4 v0 = make_float4(acc[i][0] + bias[0], acc[i][1] + bias[1],
                                acc[i][2] + bias[2], acc[i][3] + bias[3]);
        float4 v1 = make_float4(acc[i][4] + bias[4], acc[i][5] + bias[5],
                                acc[i][6] + bias[6], acc[i][7] + bias[7]);
        *(float4*)&out[(size_t)(m0 + r0 + i) * DD + n0 + c0]     = v0;
        *(float4*)&out[(size_t)(m0 + r0 + i) * DD + n0 + c0 + 4] = v1;
    }
}

// ---------------------------------------------------------------------------
extern "C" void kernel_launch(void* const* d_in, const int* in_sizes, int n_in,
                              void* d_out, int out_size)
{
    const float* x  = (const float*)d_in[0];
    const float* Wq = (const float*)d_in[1];
    const float* Wk = (const float*)d_in[2];
    const float* Wv = (const float*)d_in[3];
    const float* Wp = (const float*)d_in[4];
    const float* bp = (const float*)d_in[5];
    float* out = (float*)d_out;

    qkv_kernel<<<dim3(MM / 256, 48), 256>>>(x, Wq, Wk, Wv);
    attn_kernel<<<dim3(TT / 64, BB * HH), 256>>>();
    proj_kernel<<<dim3(MM / 128, DD / 128), 256>>>(Wp, bp, out);
}

// round 12
// speedup vs baseline: 1.1053x; 1.1053x over previous
#include <cuda_runtime.h>
#include <math.h>

#define BB 4
#define TT 2048
#define DD 1024
#define HH 16
#define HDIM 64
#define MM (BB*TT)   // 8192

// Scratch (device globals — no allocations allowed)
__device__ float g_q[BB*HH*TT*HDIM];   // [B,H,T,HD] 32MB
__device__ float g_k[BB*HH*TT*HDIM];
__device__ float g_v[BB*HH*TT*HDIM];
__device__ float g_o[BB*TT*HH*HDIM];   // [B,T,H*HD] 32MB

// Single-instruction exp2 (MUFU.EX2) independent of nvcc fast-math flags.
__device__ __forceinline__ float ex2(float x) {
    float r;
    asm("ex2.approx.ftz.f32 %0, %1;" : "=f"(r) : "f"(x));
    return r;
}

// ---------------------------------------------------------------------------
// Kernel 1: QKV projection.  For each (mat in {q,k,v}, head h):
//   out[8192, 64] = X[8192, 1024] @ W_h[1024, 64]
// BM=256, BN=64, BK=16, 256 threads, 8x8 accumulators, double-buffered SMEM.
// A tile stored TRANSPOSED (Ast[kk][row], stride 260 = 16B-aligned) so the
// 8 a-loads are 2x LDS.128 conflict-free; Ws rows padded to 68 floats
// (16B-aligned) so b-loads are 2x LDS.128.  Prefetch: batched LDGs (MLP=5)
// then STS into the other buffer; staging temps die before the FMA block.
// ---------------------------------------------------------------------------
__global__ __launch_bounds__(256, 2) void qkv_kernel(
    const float* __restrict__ x,
    const float* __restrict__ Wq,
    const float* __restrict__ Wk,
    const float* __restrict__ Wv)
{
    __shared__ float Ast[2][16][260];  // 33280 B  (transposed A: [kk][row])
    __shared__ float Ws[2][16][68];    //  8704 B

    const int tid = threadIdx.x;
    const int mat = blockIdx.y >> 4;    // 0=q,1=k,2=v
    const int h   = blockIdx.y & 15;
    const float* W = (mat == 0 ? Wq : (mat == 1 ? Wk : Wv)) + (size_t)h * DD * HDIM;
    float* outp = (mat == 0 ? g_q : (mat == 1 ? g_k : g_v));

    const int m0 = blockIdx.x * 256;
    const int tx = tid & 7;       // 8 col groups
    const int ty = tid >> 3;      // 32 row groups
    const int r0 = ty * 8;
    const int c0 = tx * 8;

    const int a_row = tid >> 2;        // 0..63 (base row per 64-row chunk)
    const int a_c4  = tid & 3;         // which 4-float k-slice
    const int w_row = tid >> 4;
    const int w_c4  = tid & 15;

    float acc[8][8];
#pragma unroll
    for (int i = 0; i < 8; i++)
#pragma unroll
        for (int j = 0; j < 8; j++) acc[i][j] = 0.0f;

    // Preload k0 = 0 into buffer 0 (A transposed)
    {
        float4 rA[4], rW;
#pragma unroll
        for (int l = 0; l < 4; l++)
            rA[l] = *(const float4*)&x[(size_t)(m0 + l * 64 + a_row) * DD + a_c4 * 4];
        rW = *(const float4*)&W[(size_t)w_row * HDIM + w_c4 * 4];
#pragma unroll
        for (int l = 0; l < 4; l++) {
            int row = l * 64 + a_row;
            Ast[0][a_c4 * 4 + 0][row] = rA[l].x;
            Ast[0][a_c4 * 4 + 1][row] = rA[l].y;
            Ast[0][a_c4 * 4 + 2][row] = rA[l].z;
            Ast[0][a_c4 * 4 + 3][row] = rA[l].w;
        }
        *(float4*)&Ws[0][w_row][w_c4 * 4] = rW;
    }
    __syncthreads();

    int buf = 0;
    for (int k0 = 0; k0 < DD; k0 += 16) {
        const bool has_next = (k0 + 16) < DD;

        if (has_next) {
            const int nb = buf ^ 1;
            float4 rA[4], rW;
#pragma unroll
            for (int l = 0; l < 4; l++)
                rA[l] = *(const float4*)&x[(size_t)(m0 + l * 64 + a_row) * DD + (k0 + 16) + a_c4 * 4];
            rW = *(const float4*)&W[(size_t)(k0 + 16 + w_row) * HDIM + w_c4 * 4];
#pragma unroll
            for (int l = 0; l < 4; l++) {
                int row = l * 64 + a_row;
                Ast[nb][a_c4 * 4 + 0][row] = rA[l].x;
                Ast[nb][a_c4 * 4 + 1][row] = rA[l].y;
                Ast[nb][a_c4 * 4 + 2][row] = rA[l].z;
                Ast[nb][a_c4 * 4 + 3][row] = rA[l].w;
            }
            *(float4*)&Ws[nb][w_row][w_c4 * 4] = rW;
        }

#pragma unroll
        for (int kk = 0; kk < 16; kk++) {
            float4 a0 = *(const float4*)&Ast[buf][kk][r0];
            float4 a1 = *(const float4*)&Ast[buf][kk][r0 + 4];
            float4 b0 = *(const float4*)&Ws[buf][kk][c0];
            float4 b1 = *(const float4*)&Ws[buf][kk][c0 + 4];
            float a[8] = {a0.x, a0.y, a0.z, a0.w, a1.x, a1.y, a1.z, a1.w};
            float b[8] = {b0.x, b0.y, b0.z, b0.w, b1.x, b1.y, b1.z, b1.w};
#pragma unroll
            for (int i = 0; i < 8; i++)
#pragma unroll
                for (int j = 0; j < 8; j++) acc[i][j] = fmaf(a[i], b[j], acc[i][j]);
        }

        if (has_next) {
            __syncthreads();
            buf ^= 1;
        }
    }

    // Store to [B,H,T,HD]
    const int b_ = m0 / TT;
    const int t0 = m0 % TT;
    const int bh = b_ * HH + h;
    float* obase = outp + ((size_t)bh * TT + t0) * HDIM;
#pragma unroll
    for (int i = 0; i < 8; i++) {
        float4 v0 = make_float4(acc[i][0], acc[i][1], acc[i][2], acc[i][3]);
        float4 v1 = make_float4(acc[i][4], acc[i][5], acc[i][6], acc[i][7]);
        *(float4*)&obase[(size_t)(r0 + i) * HDIM + c0]     = v0;
        *(float4*)&obase[(size_t)(r0 + i) * HDIM + c0 + 4] = v1;
    }
}

// ---------------------------------------------------------------------------
// Kernel 2: causal flash attention, fp32 online softmax in base-2 domain.
// Grid: (32 q-tiles, 64 bh).  Block: 256 threads.
// Thread (r = tid>>2, g = tid&3) owns query row r, dims/cols [g*16, g*16+16).
// Q (pre-scaled by log2(e)/sqrt(HD)) in registers, shfl-broadcast across the
// 4-lane group; K transposed in SMEM; P broadcast by shfl (never in SMEM).
// SMEM loads in both hot loops are g-only addressed -> warp-broadcast (N=1).
// K/V tiles for step kt+1 are register-prefetched during compute on step kt.
// ---------------------------------------------------------------------------
__global__ __launch_bounds__(256, 2) void attn_kernel()
{
    __shared__ float Kts[HDIM][68];  // [dim][key], padded
    __shared__ float Vs[64][64];     // [key][dim]

    const int tid = threadIdx.x;
    const int r = tid >> 2;
    const int g = tid & 3;
    const int qt = gridDim.x - 1 - blockIdx.x;  // heavy diagonals first
    const int bh = blockIdx.y;

    const float* kbp = g_k + (size_t)bh * TT * HDIM;
    const float* vbp = g_v + (size_t)bh * TT * HDIM;
    const int qrow = qt * 64 + r;
    // scale = log2(e) / sqrt(64): softmax computed as 2^(s - m) with s in
    // log2-units, identical to exp((qk/8) - m_e) since 2^(x*log2e) == e^x.
    const float scale = 0.125f * 1.4426950408889634f;

    // Per-thread tile-load coordinates: 4 (s, e4) chunks
    const int ld_s  = tid >> 4;   // 0..15 (base key row per 16-row chunk)
    const int ld_e4 = tid & 15;   // 0..15 (float4 slot within 64-dim row)

    // Q row slice into registers, pre-scaled
    float qreg[16];
    {
        const float* qp = g_q + ((size_t)bh * TT + qrow) * HDIM + g * 16;
#pragma unroll
        for (int i = 0; i < 4; i++) {
            float4 v = *(const float4*)(qp + i * 4);
            qreg[i * 4 + 0] = v.x * scale; qreg[i * 4 + 1] = v.y * scale;
            qreg[i * 4 + 2] = v.z * scale; qreg[i * 4 + 3] = v.w * scale;
        }
    }

    float o[16];
#pragma unroll
    for (int i = 0; i < 16; i++) o[i] = 0.0f;
    float m_prev = -1e30f;
    float l = 0.0f;

    // Prefetch tile 0 into registers
    float4 pK[4], pV[4];
#pragma unroll
    for (int l4 = 0; l4 < 4; l4++) {
        int s = l4 * 16 + ld_s;
        pK[l4] = *(const float4*)&kbp[(size_t)s * HDIM + ld_e4 * 4];
        pV[l4] = *(const float4*)&vbp[(size_t)s * HDIM + ld_e4 * 4];
    }

    for (int kt = 0; kt <= qt; kt++) {
        // Store prefetched regs into SMEM (K transposed)
#pragma unroll
        for (int l4 = 0; l4 < 4; l4++) {
            int s = l4 * 16 + ld_s;
            Kts[ld_e4 * 4 + 0][s] = pK[l4].x;
            Kts[ld_e4 * 4 + 1][s] = pK[l4].y;
            Kts[ld_e4 * 4 + 2][s] = pK[l4].z;
            Kts[ld_e4 * 4 + 3][s] = pK[l4].w;
            *(float4*)&Vs[s][ld_e4 * 4] = pV[l4];
        }
        __syncthreads();

        // Issue prefetch for next tile (results consumed after compute+sync)
        if (kt < qt) {
#pragma unroll
            for (int l4 = 0; l4 < 4; l4++) {
                int s = (kt + 1) * 64 + l4 * 16 + ld_s;
                pK[l4] = *(const float4*)&kbp[(size_t)s * HDIM + ld_e4 * 4];
                pV[l4] = *(const float4*)&vbp[(size_t)s * HDIM + ld_e4 * 4];
            }
        }

        // Scores: sacc[j] = sum_k Q[r][k] * K[kt*64 + g*16+j][k]  (log2-units)
        float sacc[16];
#pragma unroll
        for (int j = 0; j < 16; j++) sacc[j] = 0.0f;
#pragma unroll
        for (int kb4 = 0; kb4 < 4; kb4++) {
#pragma unroll
            for (int ki = 0; ki < 16; ki++) {
                float qv = __shfl_sync(0xffffffffu, qreg[ki], kb4, 4);
                int k = kb4 * 16 + ki;
                float4 k0 = *(const float4*)&Kts[k][g * 16 + 0];
                float4 k1 = *(const float4*)&Kts[k][g * 16 + 4];
                float4 k2 = *(const float4*)&Kts[k][g * 16 + 8];
                float4 k3 = *(const float4*)&Kts[k][g * 16 + 12];
                sacc[0]  = fmaf(qv, k0.x, sacc[0]);
                sacc[1]  = fmaf(qv, k0.y, sacc[1]);
                sacc[2]  = fmaf(qv, k0.z, sacc[2]);
                sacc[3]  = fmaf(qv, k0.w, sacc[3]);
                sacc[4]  = fmaf(qv, k1.x, sacc[4]);
                sacc[5]  = fmaf(qv, k1.y, sacc[5]);
                sacc[6]  = fmaf(qv, k1.z, sacc[6]);
                sacc[7]  = fmaf(qv, k1.w, sacc[7]);
                sacc[8]  = fmaf(qv, k2.x, sacc[8]);
                sacc[9]  = fmaf(qv, k2.y, sacc[9]);
                sacc[10] = fmaf(qv, k2.z, sacc[10]);
                sacc[11] = fmaf(qv, k2.w, sacc[11]);
                sacc[12] = fmaf(qv, k3.x, sacc[12]);
                sacc[13] = fmaf(qv, k3.y, sacc[13]);
                sacc[14] = fmaf(qv, k3.z, sacc[14]);
                sacc[15] = fmaf(qv, k3.w, sacc[15]);
            }
        }

        // Causal mask (diagonal tile only; scale already folded into Q)
        if (kt == qt) {
#pragma unroll
            for (int j = 0; j < 16; j++) {
                int s_local = g * 16 + j;
                if (s_local > r) sacc[j] = -1e30f;
            }
        }

        // Online softmax in base-2 (row state shared across the 4-lane group)
        float mloc = sacc[0];
#pragma unroll
        for (int j = 1; j < 16; j++) mloc = fmaxf(mloc, sacc[j]);
        mloc = fmaxf(mloc, __shfl_xor_sync(0xffffffffu, mloc, 1));
        mloc = fmaxf(mloc, __shfl_xor_sync(0xffffffffu, mloc, 2));
        float m_new = fmaxf(m_prev, mloc);
        float corr = ex2(m_prev - m_new);
        float sum = 0.0f;
#pragma unroll
        for (int j = 0; j < 16; j++) {
            sacc[j] = ex2(sacc[j] - m_new);
            sum += sacc[j];
        }
        sum += __shfl_xor_sync(0xffffffffu, sum, 1);
        sum += __shfl_xor_sync(0xffffffffu, sum, 2);
        l = l * corr + sum;
#pragma unroll
        for (int j = 0; j < 16; j++) o[j] *= corr;
        m_prev = m_new;

        // O += P @ V  (P broadcast within the 4-lane row group via shfl)
#pragma unroll
        for (int sb = 0; sb < 4; sb++) {
#pragma unroll
            for (int si = 0; si < 16; si++) {
                float p = __shfl_sync(0xffffffffu, sacc[si], sb, 4);
                int s = sb * 16 + si;
                float4 v0 = *(const float4*)&Vs[s][g * 16 + 0];
                float4 v1 = *(const float4*)&Vs[s][g * 16 + 4];
                float4 v2 = *(const float4*)&Vs[s][g * 16 + 8];
                float4 v3 = *(const float4*)&Vs[s][g * 16 + 12];
                o[0]  = fmaf(p, v0.x, o[0]);
                o[1]  = fmaf(p, v0.y, o[1]);
                o[2]  = fmaf(p, v0.z, o[2]);
                o[3]  = fmaf(p, v0.w, o[3]);
                o[4]  = fmaf(p, v1.x, o[4]);
                o[5]  = fmaf(p, v1.y, o[5]);
                o[6]  = fmaf(p, v1.z, o[6]);
                o[7]  = fmaf(p, v1.w, o[7]);
                o[8]  = fmaf(p, v2.x, o[8]);
                o[9]  = fmaf(p, v2.y, o[9]);
                o[10] = fmaf(p, v2.z, o[10]);
                o[11] = fmaf(p, v2.w, o[11]);
                o[12] = fmaf(p, v3.x, o[12]);
                o[13] = fmaf(p, v3.y, o[13]);
                o[14] = fmaf(p, v3.z, o[14]);
                o[15] = fmaf(p, v3.w, o[15]);
            }
        }
        __syncthreads();  // all reads of this tile done before overwrite
    }

    // Normalize and write to [B,T,H*HD] concat layout
    const float inv = 1.0f / l;
    const int b_ = bh >> 4;
    const int h  = bh & 15;
    float* op = g_o + (((size_t)(b_ * TT + qrow)) * HH + h) * HDIM + g * 16;
#pragma unroll
    for (int i = 0; i < 4; i++) {
        float4 v = make_float4(o[i * 4 + 0] * inv, o[i * 4 + 1] * inv,
                               o[i * 4 + 2] * inv, o[i * 4 + 3] * inv);
        *(float4*)(op + i * 4) = v;
    }
}

// ---------------------------------------------------------------------------
// Kernel 3: output projection.  out[8192,1024] = g_o[8192,1024] @ Wp[1024,1024] + bp
// BM=128, BN=128, BK=16, 256 threads, 8x8 accumulators, double-buffered SMEM.
// Transposed A tile (Ast[kk][row], stride 132) + 16B-aligned Ws (stride 132):
// both a- and b-loads are 2x LDS.128 (was 16 scalar LDS with 4-way conflicts).
// ---------------------------------------------------------------------------
__global__ __launch_bounds__(256, 2) void proj_kernel(
    const float* __restrict__ Wp,
    const float* __restrict__ bp,
    float* __restrict__ out)
{
    __shared__ float Ast[2][16][132];  // 16896 B (transposed A: [kk][row])
    __shared__ float Ws[2][16][132];   // 16896 B

    const int tid = threadIdx.x;
    const int m0 = blockIdx.x * 128;
    const int n0 = blockIdx.y * 128;
    const int tx = tid & 15;      // 16 col groups
    const int ty = tid >> 4;      // 16 row groups
    const int r0 = ty * 8;
    const int c0 = tx * 8;

    const int a_row = tid >> 2;   // 0..63
    const int a_c4  = tid & 3;
    const int w_row = tid >> 5;   // 0..7
    const int w_c4  = tid & 31;

    float acc[8][8];
#pragma unroll
    for (int i = 0; i < 8; i++)
#pragma unroll
        for (int j = 0; j < 8; j++) acc[i][j] = 0.0f;

    // Preload k0 = 0
    {
        float4 rA[2], rW[2];
#pragma unroll
        for (int l = 0; l < 2; l++)
            rA[l] = *(const float4*)&g_o[(size_t)(m0 + l * 64 + a_row) * DD + a_c4 * 4];
#pragma unroll
        for (int l = 0; l < 2; l++)
            rW[l] = *(const float4*)&Wp[(size_t)(l * 8 + w_row) * DD + n0 + w_c4 * 4];
#pragma unroll
        for (int l = 0; l < 2; l++) {
            int row = l * 64 + a_row;
            Ast[0][a_c4 * 4 + 0][row] = rA[l].x;
            Ast[0][a_c4 * 4 + 1][row] = rA[l].y;
            Ast[0][a_c4 * 4 + 2][row] = rA[l].z;
            Ast[0][a_c4 * 4 + 3][row] = rA[l].w;
        }
#pragma unroll
        for (int l = 0; l < 2; l++)
            *(float4*)&Ws[0][l * 8 + w_row][w_c4 * 4] = rW[l];
    }
    __syncthreads();

    int buf = 0;
    for (int k0 = 0; k0 < DD; k0 += 16) {
        const bool has_next = (k0 + 16) < DD;

        if (has_next) {
            const int nb = buf ^ 1;
            float4 rA[2], rW[2];
#pragma unroll
            for (int l = 0; l < 2; l++)
                rA[l] = *(const float4*)&g_o[(size_t)(m0 + l * 64 + a_row) * DD + (k0 + 16) + a_c4 * 4];
#pragma unroll
            for (int l = 0; l < 2; l++)
                rW[l] = *(const float4*)&Wp[(size_t)(k0 + 16 + l * 8 + w_row) * DD + n0 + w_c4 * 4];
#pragma unroll
            for (int l = 0; l < 2; l++) {
                int row = l * 64 + a_row;
                Ast[nb][a_c4 * 4 + 0][row] = rA[l].x;
                Ast[nb][a_c4 * 4 + 1][row] = rA[l].y;
                Ast[nb][a_c4 * 4 + 2][row] = rA[l].z;
                Ast[nb][a_c4 * 4 + 3][row] = rA[l].w;
            }
#pragma unroll
            for (int l = 0; l < 2; l++)
                *(float4*)&Ws[nb][l * 8 + w_row][w_c4 * 4] = rW[l];
        }

#pragma unroll
        for (int kk = 0; kk < 16; kk++) {
            float4 a0 = *(const float4*)&Ast[buf][kk][r0];
            float4 a1 = *(const float4*)&Ast[buf][kk][r0 + 4];
            float4 b0 = *(const float4*)&Ws[buf][kk][c0];
            float4 b1 = *(const float4*)&Ws[buf][kk][c0 + 4];
            float a[8] = {a0.x, a0.y, a0.z, a0.w, a1.x, a1.y, a1.z, a1.w};
            float b[8] = {b0.x, b0.y, b0.z, b0.w, b1.x, b1.y, b1.z, b1.w};
#pragma unroll
            for (int i = 0; i < 8; i++)
#pragma unroll
                for (int j = 0; j < 8; j++) acc[i][j] = fmaf(a[i], b[j], acc[i][j]);
        }

        if (has_next) {
            __syncthreads();
            buf ^= 1;
        }
    }

    float bias[8];
#pragma unroll
    for (int j = 0; j < 8; j++) bias[j] = bp[n0 + c0 + j];
#pragma unroll
    for (int i = 0; i < 8; i++) {
        float4 v0 = make_float4(acc[i][0] + bias[0], acc[i][1] + bias[1],
                                acc[i][2] + bias[2], acc[i][3] + bias[3]);
        float4 v1 = make_float4(acc[i][4] + bias[4], acc[i][5] + bias[5],
                                acc[i][6] + bias[6], acc[i][7] + bias[7]);
        *(float4*)&out[(size_t)(m0 + r0 + i) * DD + n0 + c0]     = v0;
        *(float4*)&out[(size_t)(m0 + r0 + i) * DD + n0 + c0 + 4] = v1;
    }
}

// ---------------------------------------------------------------------------
extern "C" void kernel_launch(void* const* d_in, const int* in_sizes, int n_in,
                              void* d_out, int out_size)
{
    const float* x  = (const float*)d_in[0];
    const float* Wq = (const float*)d_in[1];
    const float* Wk = (const float*)d_in[2];
    const float* Wv = (const float*)d_in[3];
    const float* Wp = (const float*)d_in[4];
    const float* bp = (const float*)d_in[5];
    float* out = (float*)d_out;

    qkv_kernel<<<dim3(MM / 256, 48), 256>>>(x, Wq, Wk, Wv);
    attn_kernel<<<dim3(TT / 64, BB * HH), 256>>>();
    proj_kernel<<<dim3(MM / 128, DD / 128), 256>>>(Wp, bp, out);
}